// round 16
// baseline (speedup 1.0000x reference)
#include <cuda_runtime.h>
#include <cuda_fp16.h>
#include <cstdint>
#include <math.h>

#define BATCH   4
#define QLEN    512
#define KVLEN   4096
#define DMODEL  1024
#define NHEAD   16
#define DH      64
#define GK      1024
#define NKV     (BATCH * KVLEN)

// ---------------- scratch (allocation-free rule) ----------------
__device__ __half g_mh [BATCH * KVLEN * DMODEL];
__device__ __half g_qh [BATCH * QLEN  * DMODEL];
__device__ __half g_ah [BATCH * QLEN  * DMODEL];
__device__ __half g_wh [4][DMODEL * DMODEL];
__device__ __half g_wl [4][DMODEL * DMODEL];
__device__ __half g_pqh[BATCH * QLEN  * DMODEL];
__device__ __half g_pkh[BATCH * KVLEN * DMODEL];
__device__ __half g_vth[DMODEL * NKV];

#define CP_ASYNC16(d, s) asm volatile("cp.async.cg.shared.global [%0], [%1], 16;" :: "r"(d), "l"(s))
#define LDSM_X4(r, a) \
    asm volatile("ldmatrix.sync.aligned.m8n8.x4.shared.b16 {%0,%1,%2,%3}, [%4];" \
        : "=r"((r)[0]), "=r"((r)[1]), "=r"((r)[2]), "=r"((r)[3]) : "r"(a))

__device__ __forceinline__ void mma_f16(float* c, const uint32_t* a, const uint32_t* b) {
    asm volatile(
        "mma.sync.aligned.m16n8k16.row.col.f32.f16.f16.f32 "
        "{%0,%1,%2,%3}, {%4,%5,%6,%7}, {%8,%9}, {%0,%1,%2,%3};"
        : "+f"(c[0]), "+f"(c[1]), "+f"(c[2]), "+f"(c[3])
        : "r"(a[0]), "r"(a[1]), "r"(a[2]), "r"(a[3]), "r"(b[0]), "r"(b[1]));
}

// ---------------- preps ----------------
__global__ void k_prep(const float* __restrict__ query, const float* __restrict__ memory)
{
    const int n_q  = BATCH * QLEN  * DMODEL;
    const int n_kv = BATCH * KVLEN * DMODEL;
    for (int i = blockIdx.x * blockDim.x + threadIdx.x; i < n_q + n_kv;
         i += gridDim.x * blockDim.x) {
        if (i < n_q) g_qh[i] = __float2half_rn(query[i]);
        else         g_mh[i - n_q] = __float2half_rn(memory[i - n_q]);
    }
}
__global__ void k_tsplit4(const float* __restrict__ W0, const float* __restrict__ W1,
                          const float* __restrict__ W2, const float* __restrict__ W3)
{
    __shared__ float t[32][33];
    const float* Ws[4] = {W0, W1, W2, W3};
    int w = blockIdx.z;
    const float* W = Ws[w];
    __half* Th = g_wh[w];
    __half* Tl = g_wl[w];
    const bool need_lo = (w == 0) || (w == 3);
    int k0 = blockIdx.y * 32, n0 = blockIdx.x * 32;
    int tx = threadIdx.x, ty = threadIdx.y;
#pragma unroll
    for (int i = 0; i < 4; i++)
        t[ty + 8 * i][tx] = W[(size_t)(k0 + ty + 8 * i) * DMODEL + n0 + tx];
    __syncthreads();
#pragma unroll
    for (int i = 0; i < 4; i++) {
        float v = t[tx][ty + 8 * i];
        __half h = __float2half_rn(v);
        size_t o = (size_t)(n0 + ty + 8 * i) * DMODEL + k0 + tx;
        Th[o] = h;
        if (need_lo) Tl[o] = __float2half_rn(v - __half2float(h));
    }
}

// ---------------------------------------------------------------------------
// fp16 GEMM body. NB=2: hi+lo B, 2-stage ring. NB=1: hi B, 3-stage ring.
// CTA 128x128, BK=64, one barrier per k-tile, ldmatrix fragments.
// ---------------------------------------------------------------------------
#define SKW   36
#define ARR_W (128 * SKW)
#define GEMM_SMEM (2 * 3 * ARR_W * 4)     // 110592 B (both variants fit)

struct GemmAcc { float a[4][4][4]; };

template<int NB>
__device__ __forceinline__ void gemm_body(
    uint32_t* sm32, const __half* A, const __half* Bh, const __half* Bl,
    int bm, int bn, GemmAcc& acc_)
{
    constexpr int NARR   = 1 + NB;
    constexpr int STAGES = (NB == 1) ? 3 : 2;
    constexpr int BUF_W  = NARR * ARR_W;

    const int tid  = threadIdx.x;
    const int wid  = tid >> 5, lane = tid & 31;
    const int r8   = lane & 7, sub = lane >> 3;
    const int wm64 = (wid & 1) * 64;
    const int wn32 = (wid >> 1) * 32;

    const size_t arow0 = (size_t)bm * 128 * GK;
    const size_t brow0 = (size_t)bn * 128 * GK;
    const uint32_t smem_b = (uint32_t)__cvta_generic_to_shared(sm32);

    const int a_row = wm64 + r8 + ((sub & 1) << 3);
    const int a_col = (sub >> 1) << 2;
    const int b_row2 = wn32 + r8;
    const int b_col  = ((sub & 1) << 2);
    const int b_arr2 = ARR_W + (sub >> 1) * ARR_W;
    const int b_row1 = wn32 + ((sub >> 1) << 3) + r8;

    float (*acc)[4][4] = acc_.a;
#pragma unroll
    for (int mt = 0; mt < 4; mt++)
#pragma unroll
        for (int nt = 0; nt < 4; nt++)
#pragma unroll
            for (int r = 0; r < 4; r++) acc[mt][nt][r] = 0.f;

    auto load_tile = [&](int kt, int slot) {
        const __half* srcs[3] = { A + arow0 + kt * 64, Bh + brow0 + kt * 64,
                                  NB == 2 ? Bl + brow0 + kt * 64 : Bh };
#pragma unroll
        for (int i = 0; i < 4 * NARR; i++) {
            int chunk = tid + 256 * i;
            int arr = chunk >> 10;
            int w   = chunk & 1023;
            int row = w >> 3, c = w & 7;
            uint32_t dst = smem_b + ((slot * BUF_W + arr * ARR_W + row * SKW + c * 4) << 2);
            CP_ASYNC16(dst, srcs[arr] + (size_t)row * GK + c * 8);
        }
        asm volatile("cp.async.commit_group;");
    };

    load_tile(0, 0);
    if (STAGES == 3) load_tile(1, 1);

    const int NT = GK / 64;
    for (int kt = 0; kt < NT; kt++) {
        const int slot = kt % STAGES;
        if (STAGES == 3 && kt < NT - 1) asm volatile("cp.async.wait_group 1;");
        else                            asm volatile("cp.async.wait_group 0;");
        __syncthreads();
        if (kt + STAGES - 1 < NT) load_tile(kt + STAGES - 1, (kt + STAGES - 1) % STAGES);

        const uint32_t bufw = slot * BUF_W;
#pragma unroll
        for (int ks = 0; ks < 4; ks++) {
            uint32_t bf[4][4];
            if (NB == 2) {
#pragma unroll
                for (int nt = 0; nt < 4; nt++)
                    LDSM_X4(bf[nt], smem_b + ((bufw + b_arr2 + (b_row2 + nt * 8) * SKW + ks * 8 + b_col) << 2));
            } else {
#pragma unroll
                for (int np = 0; np < 2; np++)
                    LDSM_X4(bf[np], smem_b + ((bufw + ARR_W + (b_row1 + np * 16) * SKW + ks * 8 + b_col) << 2));
            }
#pragma unroll
            for (int mt = 0; mt < 4; mt++) {
                uint32_t ah[4];
                LDSM_X4(ah, smem_b + ((bufw + (a_row + mt * 16) * SKW + ks * 8 + a_col) << 2));
                if (NB == 2) {
#pragma unroll
                    for (int nt = 0; nt < 4; nt++) {
                        mma_f16(acc[mt][nt], ah, bf[nt]);
                        mma_f16(acc[mt][nt], ah, bf[nt] + 2);
                    }
                } else {
#pragma unroll
                    for (int np = 0; np < 2; np++) {
                        mma_f16(acc[mt][2 * np],     ah, bf[np]);
                        mma_f16(acc[mt][2 * np + 1], ah, bf[np] + 2);
                    }
                }
            }
        }
    }
}

// Unified projections: Q (2-term) | K (1-term) | V transposed (1-term).
__global__ __launch_bounds__(256, 2)
void k_proj()
{
    extern __shared__ __align__(16) uint32_t sm32[];
    const int id = blockIdx.x;

    GemmAcc acc_;
    __half* Chi;
    int ldC, bm, bn;
    if (id < 128) {
        bm = id >> 3; bn = id & 7; ldC = DMODEL; Chi = g_pqh;
        gemm_body<2>(sm32, g_qh, g_wh[0], g_wl[0], bm, bn, acc_);
    } else if (id < 1152) {
        int q = id - 128;
        bm = q >> 3; bn = q & 7; ldC = DMODEL; Chi = g_pkh;
        gemm_body<1>(sm32, g_mh, g_wh[1], nullptr, bm, bn, acc_);
    } else {
        int q = id - 1152;
        bm = q >> 7; bn = q & 127; ldC = NKV; Chi = g_vth;
        gemm_body<1>(sm32, g_wh[2], g_mh, nullptr, bm, bn, acc_);
    }

    const int lane = threadIdx.x & 31, wid = threadIdx.x >> 5;
    const int g = lane >> 2, tg = lane & 3;
    const int wm64 = (wid & 1) * 64, wn32 = (wid >> 1) * 32;
#pragma unroll
    for (int mt = 0; mt < 4; mt++) {
        int row0 = bm * 128 + wm64 + mt * 16 + g;
#pragma unroll
        for (int nt = 0; nt < 4; nt++) {
            int col = bn * 128 + wn32 + nt * 8 + tg * 2;
            __half2 h0 = __floats2half2_rn(acc_.a[mt][nt][0], acc_.a[mt][nt][1]);
            __half2 h1 = __floats2half2_rn(acc_.a[mt][nt][2], acc_.a[mt][nt][3]);
            *(uint32_t*)(Chi + (size_t)row0 * ldC + col)       = *(uint32_t*)&h0;
            *(uint32_t*)(Chi + (size_t)(row0 + 8) * ldC + col) = *(uint32_t*)&h1;
        }
    }
}

__global__ __launch_bounds__(256, 2)
void k_outproj(float* __restrict__ C)
{
    extern __shared__ __align__(16) uint32_t sm32[];
    const int bm = blockIdx.x >> 3, bn = blockIdx.x & 7;

    GemmAcc acc_;
    gemm_body<2>(sm32, g_ah, g_wh[3], g_wl[3], bm, bn, acc_);

    const int lane = threadIdx.x & 31, wid = threadIdx.x >> 5;
    const int g = lane >> 2, tg = lane & 3;
    const int wm64 = (wid & 1) * 64, wn32 = (wid >> 1) * 32;
#pragma unroll
    for (int mt = 0; mt < 4; mt++) {
        int row0 = bm * 128 + wm64 + mt * 16 + g;
#pragma unroll
        for (int nt = 0; nt < 4; nt++) {
            int col = bn * 128 + wn32 + nt * 8 + tg * 2;
            *(float2*)(C + (size_t)row0 * DMODEL + col)       = make_float2(acc_.a[mt][nt][0], acc_.a[mt][nt][1]);
            *(float2*)(C + (size_t)(row0 + 8) * DMODEL + col) = make_float2(acc_.a[mt][nt][2], acc_.a[mt][nt][3]);
        }
    }
}

// ---------------------------------------------------------------------------
// fp16 attention: 512 threads, q-tile 256, 4-stage ring, K/V hi-only,
// fp32 __expf softmax (full-precision argument — validated round 14).
// ---------------------------------------------------------------------------
#define AST    36
#define AQ     0
#define AKV    (256 * AST)
#define SLOT_W (2 * 64 * AST)
#define AB     (AKV + 4 * SLOT_W)
#define ATTN_SMEM ((AB + 256) * 4)

__global__ __launch_bounds__(512, 1)
void attn_mma(const float* __restrict__ bias)
{
    extern __shared__ __align__(16) uint32_t sw[];
    const uint32_t sb = (uint32_t)__cvta_generic_to_shared(sw);
    const int tid = threadIdx.x, wid = tid >> 5, lane = tid & 31;
    const int g = lane >> 2, tg = lane & 3;
    const int r8 = lane & 7, sub = lane >> 3;
    const int qt = blockIdx.x, h = blockIdx.y, b = blockIdx.z;
    const int q0 = qt * 256;
    const int qrow = wid * 16;

    const int a_row = qrow + r8 + ((sub & 1) << 3);
    const int a_col = (sub >> 1) << 2;
    const int pb_row = ((sub >> 1) << 3) + r8;
    const int pb_col = ((sub & 1) << 2);

    // ---- Q load ----
    {
        const __half* s0 = g_pqh + ((size_t)(b * QLEN + q0)) * DMODEL + h * DH;
#pragma unroll
        for (int i = 0; i < 4; i++) {
            int chunk = tid + 512 * i;
            int r = chunk >> 3, c = chunk & 7;
            uint32_t dst = sb + ((AQ + r * AST + c * 4) << 2);
            CP_ASYNC16(dst, s0 + (size_t)r * DMODEL + c * 8);
        }
        asm volatile("cp.async.commit_group;");
    }

    auto load_tile = [&](int kt, int slot) {
        const int k0 = kt * 64;
        const __half* srcs[2] = {
            g_pkh + ((size_t)(b * KVLEN + k0)) * DMODEL + h * DH,
            g_vth + (size_t)(h * DH) * NKV + b * KVLEN + k0 };
        const int r = tid >> 3, c = tid & 7;
#pragma unroll
        for (int arr = 0; arr < 2; arr++) {
            size_t rstride = (arr == 0) ? DMODEL : NKV;
            uint32_t dst = sb + ((AKV + slot * SLOT_W + arr * 2304 + r * AST + c * 4) << 2);
            CP_ASYNC16(dst, srcs[arr] + (size_t)r * rstride + c * 8);
        }
        if (tid < 16) {
            uint32_t dst = sb + ((AB + slot * 64 + tid * 4) << 2);
            CP_ASYNC16(dst, bias + (size_t)b * KVLEN + k0 + tid * 4);
        }
        asm volatile("cp.async.commit_group;");
    };

    float oacc[8][4];
#pragma unroll
    for (int nt = 0; nt < 8; nt++)
#pragma unroll
        for (int r = 0; r < 4; r++) oacc[nt][r] = 0.f;
    float dsum0 = 0.f, dsum1 = 0.f;

    const int NT = KVLEN / 64;
    load_tile(0, 0);
    load_tile(1, 1);
    load_tile(2, 2);

    for (int kt = 0; kt < NT; kt++) {
        const int slot = kt & 3;
        if (kt < NT - 2)       asm volatile("cp.async.wait_group 2;");
        else if (kt == NT - 2) asm volatile("cp.async.wait_group 1;");
        else                   asm volatile("cp.async.wait_group 0;");
        __syncthreads();
        if (kt + 3 < NT) load_tile(kt + 3, (kt + 3) & 3);

        // ---- S = Q·K^T ----
        float sacc[8][4];
#pragma unroll
        for (int nt = 0; nt < 8; nt++)
#pragma unroll
            for (int r = 0; r < 4; r++) sacc[nt][r] = 0.f;

        const uint32_t kbase = AKV + slot * SLOT_W;
#pragma unroll
        for (int ks = 0; ks < 4; ks++) {
            uint32_t aH[4];
            LDSM_X4(aH, sb + ((AQ + a_row * AST + ks * 8 + a_col) << 2));
#pragma unroll
            for (int np = 0; np < 4; np++) {
                uint32_t bf[4];
                LDSM_X4(bf, sb + ((kbase + (pb_row + np * 16) * AST + ks * 8 + pb_col) << 2));
                mma_f16(sacc[2 * np],     aH, bf);
                mma_f16(sacc[2 * np + 1], aH, bf + 2);
            }
        }

        // ---- P = exp(S*scale + bias), fp32 argument ----
        const float* bsm = (const float*)(sw + AB + slot * 64);
#pragma unroll
        for (int nt = 0; nt < 8; nt++) {
            float b0 = bsm[nt * 8 + tg * 2];
            float b1 = bsm[nt * 8 + tg * 2 + 1];
            float p0 = __expf(fmaf(sacc[nt][0], 0.125f, b0));
            float p1 = __expf(fmaf(sacc[nt][1], 0.125f, b1));
            float p2 = __expf(fmaf(sacc[nt][2], 0.125f, b0));
            float p3 = __expf(fmaf(sacc[nt][3], 0.125f, b1));
            sacc[nt][0] = p0; sacc[nt][1] = p1; sacc[nt][2] = p2; sacc[nt][3] = p3;
            dsum0 += p0 + p1;
            dsum1 += p2 + p3;
        }

        // ---- O += P·V ----
        const uint32_t vbase = kbase + 2304;
#pragma unroll
        for (int ks = 0; ks < 4; ks++) {
            const float* pa = sacc[2 * ks];
            const float* pb = sacc[2 * ks + 1];
            __half2 h0 = __floats2half2_rn(pa[0], pa[1]);
            __half2 h1 = __floats2half2_rn(pa[2], pa[3]);
            __half2 h2 = __floats2half2_rn(pb[0], pb[1]);
            __half2 h3 = __floats2half2_rn(pb[2], pb[3]);
            uint32_t aP[4] = { *(uint32_t*)&h0, *(uint32_t*)&h1, *(uint32_t*)&h2, *(uint32_t*)&h3 };
#pragma unroll
            for (int np = 0; np < 4; np++) {
                uint32_t bf[4];
                LDSM_X4(bf, sb + ((vbase + (pb_row + np * 16) * AST + ks * 8 + pb_col) << 2));
                mma_f16(oacc[2 * np],     aP, bf);
                mma_f16(oacc[2 * np + 1], aP, bf + 2);
            }
        }
    }

    // ---- denominators (quad reduce) ----
    dsum0 += __shfl_xor_sync(0xFFFFFFFFu, dsum0, 1);
    dsum0 += __shfl_xor_sync(0xFFFFFFFFu, dsum0, 2);
    dsum1 += __shfl_xor_sync(0xFFFFFFFFu, dsum1, 1);
    dsum1 += __shfl_xor_sync(0xFFFFFFFFu, dsum1, 2);
    const float inv0 = 1.f / dsum0, inv1 = 1.f / dsum1;

    const int row = b * QLEN + q0 + qrow + g;
#pragma unroll
    for (int nt = 0; nt < 8; nt++) {
        const int col = h * DH + nt * 8 + tg * 2;
        __half2 o0 = __floats2half2_rn(oacc[nt][0] * inv0, oacc[nt][1] * inv0);
        __half2 o1 = __floats2half2_rn(oacc[nt][2] * inv1, oacc[nt][3] * inv1);
        *(uint32_t*)(g_ah + (size_t)row * DMODEL + col)       = *(uint32_t*)&o0;
        *(uint32_t*)(g_ah + (size_t)(row + 8) * DMODEL + col) = *(uint32_t*)&o1;
    }
}

// ---------------------------------------------------------------------------
extern "C" void kernel_launch(void* const* d_in, const int* in_sizes, int n_in,
                              void* d_out, int out_size)
{
    const float* query  = (const float*)d_in[0];
    const float* memory = (const float*)d_in[1];
    const float* bias   = (const float*)d_in[2];
    const float* Wq     = (const float*)d_in[3];
    const float* Wk     = (const float*)d_in[4];
    const float* Wv     = (const float*)d_in[5];
    const float* Wo     = (const float*)d_in[6];
    float* out = (float*)d_out;

    cudaFuncSetAttribute(k_proj,    cudaFuncAttributeMaxDynamicSharedMemorySize, GEMM_SMEM);
    cudaFuncSetAttribute(k_outproj, cudaFuncAttributeMaxDynamicSharedMemorySize, GEMM_SMEM);
    cudaFuncSetAttribute(attn_mma,  cudaFuncAttributeMaxDynamicSharedMemorySize, ATTN_SMEM);

    k_prep<<<4096, 256>>>(query, memory);
    k_tsplit4<<<dim3(DMODEL / 32, DMODEL / 32, 4), dim3(32, 8)>>>(Wq, Wk, Wv, Wo);

    k_proj<<<2176, 256, GEMM_SMEM>>>();

    attn_mma<<<dim3(QLEN / 256, NHEAD, BATCH), 512, ATTN_SMEM>>>(bias);

    k_outproj<<<128, 256, GEMM_SMEM>>>(out);
}